// round 10
// baseline (speedup 1.0000x reference)
#include <cuda_runtime.h>
#include <cuda_fp16.h>
#include <cstdint>

#define Ld    2
#define Hd    2048
#define OUTD  1024
#define Bd    64
#define Td    256
#define NCTA  128
#define THRM  512     // main kernel threads (16 warps)
#define THRP  256     // proj kernel threads
#define KC    128
#define AST   4

#define APAD  72
#define GPAD  68
#define PPAD  68
#define WPAD  136     // proj path only

// lstm_main smem
#define SMEM_A_BYTES (AST * KC * APAD * 2)        // 73728
#define SMEM_P_BYTES (7 * 64 * PPAD * 4)          // 121856
#define SMEM_G_BYTES (64 * GPAD * 4)              // 17408
#define SMEM_MAIN    (SMEM_A_BYTES + SMEM_P_BYTES + SMEM_G_BYTES)  // 212992

// proj smem
#define SMEM_A_OLD   (2 * KC * APAD * 2)
#define SMEM_W_OLD   (2 * 64 * WPAD * 2)
#define SMEM_PROJ    (SMEM_W_OLD + SMEM_A_OLD + SMEM_G_BYTES)

// ----------------------------- device globals ------------------------------
// W fragments: [l][ct][kc32][warp16][frag2][lane32] uint4  (128 MB total)
__device__ __align__(16) uint4  g_Wf[(size_t)Ld * NCTA * 32 * 16 * 2 * 32];
__device__ __align__(16) __half g_WoutH[OUTD][Hd];
__device__ float  g_bias[Ld][NCTA][64];
__device__ float  g_bout[OUTD];
__device__ __align__(16) __half g_H0[2][Hd][Bd];      // layer-0 h ping-pong [k][b]
__device__ __align__(16) __half g_H1all[Td][Hd][Bd];  // layer-1 h, all steps
__device__ __align__(16) __half g_H1init[Hd][Bd];
__device__ __align__(16) __half g_Xzero[Hd][Bd];
__device__ unsigned g_count;

// ------------------------------ PTX helpers --------------------------------
__device__ __forceinline__ unsigned sptr(const void* p) {
    return (unsigned)__cvta_generic_to_shared(p);
}
__device__ __forceinline__ void cpa16(unsigned dst, const void* src) {
    asm volatile("cp.async.cg.shared.global [%0], [%1], 16;\n" :: "r"(dst), "l"(src));
}
__device__ __forceinline__ void cpa_commit() {
    asm volatile("cp.async.commit_group;\n" ::: "memory");
}
template <int N>
__device__ __forceinline__ void cpa_wait() {
    asm volatile("cp.async.wait_group %0;\n" :: "n"(N) : "memory");
}
__device__ __forceinline__ void ldsm4(unsigned& r0, unsigned& r1, unsigned& r2,
                                      unsigned& r3, unsigned a) {
    asm volatile("ldmatrix.sync.aligned.m8n8.x4.shared.b16 {%0,%1,%2,%3},[%4];\n"
                 : "=r"(r0), "=r"(r1), "=r"(r2), "=r"(r3) : "r"(a));
}
__device__ __forceinline__ void ldsm4t(unsigned& r0, unsigned& r1, unsigned& r2,
                                       unsigned& r3, unsigned a) {
    asm volatile("ldmatrix.sync.aligned.m8n8.x4.trans.shared.b16 {%0,%1,%2,%3},[%4];\n"
                 : "=r"(r0), "=r"(r1), "=r"(r2), "=r"(r3) : "r"(a));
}
__device__ __forceinline__ void mma16816(float* d, unsigned a0, unsigned a1,
                                         unsigned a2, unsigned a3,
                                         unsigned b0, unsigned b1) {
    asm volatile(
        "mma.sync.aligned.m16n8k16.row.col.f32.f16.f16.f32 "
        "{%0,%1,%2,%3},{%4,%5,%6,%7},{%8,%9},{%0,%1,%2,%3};\n"
        : "+f"(d[0]), "+f"(d[1]), "+f"(d[2]), "+f"(d[3])
        : "r"(a0), "r"(a1), "r"(a2), "r"(a3), "r"(b0), "r"(b1));
}
__device__ __forceinline__ float sgm(float x) { return 1.f / (1.f + __expf(-x)); }

// Grid barrier: monotonic counter, reset each launch by pack_misc_kernel.
__device__ __forceinline__ void gridbar(unsigned& target) {
    __syncthreads();
    if (threadIdx.x == 0) {
        __threadfence();
        target += (unsigned)gridDim.x;
        atomicAdd(&g_count, 1u);
        unsigned v;
        for (;;) {
            asm volatile("ld.acquire.gpu.global.u32 %0, [%1];" : "=r"(v) : "l"(&g_count));
            if (v >= target) break;
            __nanosleep(32);
        }
    }
    __syncthreads();
}

// ------------------------------ prep kernels -------------------------------
// Warp wid (0..15): wm = wid&1 (32-row half), wk = wid>>1 (k16 slice of chunk).
// Frag f (0..1): mblk = f. Lane regs = W[(r,k),(r+8,k),(r,k+8),(r+8,k+8)].
__global__ void pack_w_kernel(const float* __restrict__ Wih,
                              const float* __restrict__ Whh) {
    int idx = blockIdx.x * blockDim.x + threadIdx.x;   // 8,388,608
    int lane = idx & 31;
    int f    = (idx >> 5) & 1;
    int w    = (idx >> 6) & 15;
    int kc   = (idx >> 10) & 31;
    int ct   = (idx >> 15) & 127;
    int l    = idx >> 22;
    if (l >= Ld) return;
    int wm = w & 1, wk = w >> 1;
    int r0 = wm * 32 + f * 16 + (lane >> 2);
    int k0 = kc * 128 + wk * 16 + (lane & 3) * 2;

    auto ld2 = [&](int r, int k) -> float2 {
        int grow = (r >> 4) * 2048 + ct * 16 + (r & 15);
        const float* s = (k < 2048)
            ? (Wih + ((size_t)(l * 8192 + grow)) * 2048 + k)
            : (Whh + ((size_t)(l * 8192 + grow)) * 2048 + (k - 2048));
        return *reinterpret_cast<const float2*>(s);
    };
    float2 v0 = ld2(r0,     k0);
    float2 v1 = ld2(r0 + 8, k0);
    float2 v2 = ld2(r0,     k0 + 8);
    float2 v3 = ld2(r0 + 8, k0 + 8);

    __half2 h0 = __floats2half2_rn(v0.x, v0.y);
    __half2 h1 = __floats2half2_rn(v1.x, v1.y);
    __half2 h2 = __floats2half2_rn(v2.x, v2.y);
    __half2 h3 = __floats2half2_rn(v3.x, v3.y);
    uint4 o;
    o.x = *reinterpret_cast<unsigned*>(&h0);
    o.y = *reinterpret_cast<unsigned*>(&h1);
    o.z = *reinterpret_cast<unsigned*>(&h2);
    o.w = *reinterpret_cast<unsigned*>(&h3);

    size_t off = ((((size_t)(l * NCTA + ct) * 32 + kc) * 16 + w) * 2 + f) * 32 + lane;
    g_Wf[off] = o;
}

__global__ void pack_wout_kernel(const float* __restrict__ Wout) {
    int idx = blockIdx.x * blockDim.x + threadIdx.x;
    int k0 = (idx & 511) * 4;
    int row = idx >> 9;
    if (row >= OUTD) return;
    float4 v = *reinterpret_cast<const float4*>(Wout + (size_t)row * Hd + k0);
    __half2* dst = reinterpret_cast<__half2*>(&g_WoutH[row][k0]);
    dst[0] = __floats2half2_rn(v.x, v.y);
    dst[1] = __floats2half2_rn(v.z, v.w);
}

__global__ void pack_misc_kernel(const float* __restrict__ h0,
                                 const float* __restrict__ bih,
                                 const float* __restrict__ bhh,
                                 const float* __restrict__ bout) {
    int i = blockIdx.x * blockDim.x + threadIdx.x;   // 131072
    if (i == 0) g_count = 0u;
    if (i < OUTD) g_bout[i] = bout[i];
    if (i < Ld * NCTA * 64) {
        int r = i & 63, ct = (i >> 6) & 127, l = i >> 13;
        int row = (r >> 4) * 2048 + ct * 16 + (r & 15);
        g_bias[l][ct][r] = bih[l * 8192 + row] + bhh[l * 8192 + row];
    }
    if (i < Hd * Bd) {
        int b = i & 63, j = i >> 6;
        g_H0[1][j][b]  = __float2half_rn(h0[(size_t)b * Hd + j]);
        g_H1init[j][b] = __float2half_rn(h0[(size_t)(Bd + b) * Hd + j]);
        g_Xzero[j][b]  = __float2half_rn(0.f);
    }
}

// ------------------------ gates GEMM (16 warps) ------------------------------
__device__ __forceinline__ void issueA(unsigned sAb, const __half* __restrict__ Xg,
                                       const __half* __restrict__ Hg,
                                       int chunk, int tid) {
    const __half* Ab = (chunk < 16) ? (Xg + (size_t)chunk * KC * Bd)
                                    : (Hg + (size_t)(chunk - 16) * KC * Bd);
    unsigned dstb = sAb + (unsigned)((chunk & (AST - 1)) * KC * APAD * 2);
#pragma unroll
    for (int i = 0; i < 2; i++) {
        int s = tid + i * THRM;
        int row = s >> 3, col8 = (s & 7) * 8;
        cpa16(dstb + (unsigned)((row * APAD + col8) * 2),
              Ab + (size_t)row * Bd + col8);
    }
}

__device__ __forceinline__ void gemm_gates(const uint4* __restrict__ Wf,
                                           const __half* __restrict__ Xg,
                                           const __half* __restrict__ Hg,
                                           __half* sA, float* sP, float* sG,
                                           const float* __restrict__ bias,
                                           int tid, int lane, int wid) {
    const int wm = wid & 1, wk = wid >> 1;   // wk in 0..7 (k16 slice)
    float acc[2][8][4];
#pragma unroll
    for (int a = 0; a < 2; a++)
#pragma unroll
        for (int b = 0; b < 8; b++)
#pragma unroll
            for (int c = 0; c < 4; c++) acc[a][b][c] = 0.f;

    const unsigned sAb = sptr(sA);
    const uint4* wbase = Wf + wid * 64 + lane;   // + kc*1024 + f*32

    uint4 w0[2], w1[2], w2[2];
#pragma unroll
    for (int f = 0; f < 2; f++) w0[f] = wbase[f * 32];
#pragma unroll
    for (int f = 0; f < 2; f++) w1[f] = wbase[1024 + f * 32];

#pragma unroll
    for (int pc = 0; pc < AST - 1; pc++) {
        issueA(sAb, Xg, Hg, pc, tid);
        cpa_commit();
    }

#pragma unroll 1
    for (int kc = 0; kc < 32; kc++) {
        cpa_wait<AST - 2>();
        __syncthreads();

        if (kc + AST - 1 < 32) issueA(sAb, Xg, Hg, kc + AST - 1, tid);
        cpa_commit();
        if (kc + 2 < 32) {
            const uint4* wb2 = wbase + (size_t)(kc + 2) * 1024;
#pragma unroll
            for (int f = 0; f < 2; f++) w2[f] = wb2[f * 32];
        }

        unsigned bBase = sAb + (unsigned)((((kc & (AST - 1)) * KC
                          + wk * 16 + (lane & 15)) * APAD + (lane >> 4) * 8) * 2);
#pragma unroll
        for (int nb2 = 0; nb2 < 4; nb2++) {
            unsigned b0, b1, b2, b3;
            ldsm4t(b0, b1, b2, b3, bBase + (unsigned)(nb2 * 32));
            mma16816(acc[0][nb2 * 2 + 0], w0[0].x, w0[0].y, w0[0].z, w0[0].w, b0, b1);
            mma16816(acc[0][nb2 * 2 + 1], w0[0].x, w0[0].y, w0[0].z, w0[0].w, b2, b3);
            mma16816(acc[1][nb2 * 2 + 0], w0[1].x, w0[1].y, w0[1].z, w0[1].w, b0, b1);
            mma16816(acc[1][nb2 * 2 + 1], w0[1].x, w0[1].y, w0[1].z, w0[1].w, b2, b3);
        }
#pragma unroll
        for (int f = 0; f < 2; f++) { w0[f] = w1[f]; w1[f] = w2[f]; }
    }
    __syncthreads();

    // Cross-warp reduction over wk (8-way)
    const int gid = lane >> 2, tig = lane & 3;
    if (wk > 0) {
        float* P = sP + (wk - 1) * 64 * PPAD;
#pragma unroll
        for (int mb = 0; mb < 2; mb++) {
            int r = wm * 32 + mb * 16 + gid;
#pragma unroll
            for (int nb = 0; nb < 8; nb++) {
                int c = nb * 8 + tig * 2;
                *reinterpret_cast<float2*>(&P[r * PPAD + c]) =
                    make_float2(acc[mb][nb][0], acc[mb][nb][1]);
                *reinterpret_cast<float2*>(&P[(r + 8) * PPAD + c]) =
                    make_float2(acc[mb][nb][2], acc[mb][nb][3]);
            }
        }
    }
    __syncthreads();
    if (wk == 0) {
#pragma unroll
        for (int mb = 0; mb < 2; mb++) {
            int r = wm * 32 + mb * 16 + gid;
            float bv0 = bias[r], bv1 = bias[r + 8];
#pragma unroll
            for (int nb = 0; nb < 8; nb++) {
                int c = nb * 8 + tig * 2;
                float s00 = acc[mb][nb][0] + bv0, s01 = acc[mb][nb][1] + bv0;
                float s10 = acc[mb][nb][2] + bv1, s11 = acc[mb][nb][3] + bv1;
#pragma unroll
                for (int p = 0; p < 7; p++) {
                    const float* P = sP + p * 64 * PPAD;
                    float2 u0 = *reinterpret_cast<const float2*>(&P[r * PPAD + c]);
                    float2 u1 = *reinterpret_cast<const float2*>(&P[(r + 8) * PPAD + c]);
                    s00 += u0.x; s01 += u0.y; s10 += u1.x; s11 += u1.y;
                }
                sG[r * GPAD + c]           = s00;
                sG[r * GPAD + c + 1]       = s01;
                sG[(r + 8) * GPAD + c]     = s10;
                sG[(r + 8) * GPAD + c + 1] = s11;
            }
        }
    }
    __syncthreads();
}

__device__ __forceinline__ void pointwise(const float* sG, float* cst,
                                          __half* Hout, int ct, int tid) {
#pragma unroll
    for (int e = 0; e < 2; e++) {
        int idx = tid + e * THRM;        // 16 hidden x 64 batch
        int b = idx & 63, jj = idx >> 6;
        float gi = sG[jj * GPAD + b];
        float gf = sG[(16 + jj) * GPAD + b];
        float gg = sG[(32 + jj) * GPAD + b];
        float go = sG[(48 + jj) * GPAD + b];
        float c = sgm(gf) * cst[e] + sgm(gi) * tanhf(gg);
        cst[e] = c;
        Hout[(ct * 16 + jj) * Bd + b] = __float2half_rn(sgm(go) * tanhf(c));
    }
}

// ------------------------------- main kernel -------------------------------
__global__ void __launch_bounds__(THRM, 1)
lstm_main(const float* __restrict__ c0) {
    extern __shared__ char smem[];
    __half* sA = reinterpret_cast<__half*>(smem);
    float*  sP = reinterpret_cast<float*>(smem + SMEM_A_BYTES);
    float*  sG = reinterpret_cast<float*>(smem + SMEM_A_BYTES + SMEM_P_BYTES);

    const int tid = threadIdx.x, lane = tid & 31, wid = tid >> 5;
    const int ct = blockIdx.x;

    float cst0[2], cst1[2];
#pragma unroll
    for (int e = 0; e < 2; e++) {
        int idx = tid + e * THRM;
        int b = idx & 63, j = ct * 16 + (idx >> 6);
        cst0[e] = c0[(size_t)b * Hd + j];
        cst1[e] = c0[(size_t)(Bd + b) * Hd + j];
    }

    const uint4* W0 = g_Wf + ((size_t)0 * NCTA + ct) * 32768;
    const uint4* W1 = g_Wf + ((size_t)1 * NCTA + ct) * 32768;
    const float* bias0 = &g_bias[0][ct][0];
    const float* bias1 = &g_bias[1][ct][0];
    unsigned target = 0;

    for (int t = 0; t < Td; t++) {
        const int p = t & 1;
        const __half* X0  = (t == 0) ? &g_Xzero[0][0] : &g_H1all[t - 1][0][0];
        const __half* Hp0 = &g_H0[p ^ 1][0][0];
        gemm_gates(W0, X0, Hp0, sA, sP, sG, bias0, tid, lane, wid);
        pointwise(sG, cst0, &g_H0[p][0][0], ct, tid);
        gridbar(target);

        const __half* X1  = &g_H0[p][0][0];
        const __half* Hp1 = (t == 0) ? &g_H1init[0][0] : &g_H1all[t - 1][0][0];
        gemm_gates(W1, X1, Hp1, sA, sP, sG, bias1, tid, lane, wid);
        pointwise(sG, cst1, &g_H1all[t][0][0], ct, tid);
        gridbar(target);
    }
}

// -------------------- proj GEMM (off critical path, 256 thr) ----------------
template <int KTOT>
__device__ __forceinline__ void gemm64_old(const __half* __restrict__ Wg,
                                           const __half* __restrict__ Xg,
                                           __half* sW, __half* sA, float* sG,
                                           const float* __restrict__ bias,
                                           int tid, int lane, int wid) {
    constexpr int NCHUNK = KTOT / KC;
    float acc[4][4];
#pragma unroll
    for (int i = 0; i < 4; i++)
#pragma unroll
        for (int j = 0; j < 4; j++) acc[i][j] = 0.f;
    const int wm = wid >> 1, wn = wid & 1;

    uint4 wr[4], ar[4];
#pragma unroll
    for (int i = 0; i < 4; i++) {
        int s = tid + i * THRP;
        wr[i] = *reinterpret_cast<const uint4*>(Wg + (size_t)(s >> 4) * KTOT + (s & 15) * 8);
    }
#pragma unroll
    for (int i = 0; i < 4; i++) {
        int s = tid + i * THRP;
        ar[i] = *reinterpret_cast<const uint4*>(Xg + (size_t)(s >> 3) * Bd + (s & 7) * 8);
    }

#pragma unroll 1
    for (int kc = 0; kc < NCHUNK; kc++) {
        __half* sWc = sW + (kc & 1) * 64 * WPAD;
        __half* sAc = sA + (kc & 1) * KC * APAD;
#pragma unroll
        for (int i = 0; i < 4; i++) {
            int s = tid + i * THRP;
            *reinterpret_cast<uint4*>(sWc + (s >> 4) * WPAD + (s & 15) * 8) = wr[i];
        }
#pragma unroll
        for (int i = 0; i < 4; i++) {
            int s = tid + i * THRP;
            *reinterpret_cast<uint4*>(sAc + (s >> 3) * APAD + (s & 7) * 8) = ar[i];
        }
        __syncthreads();

        if (kc + 1 < NCHUNK) {
            int k0 = (kc + 1) * KC;
#pragma unroll
            for (int i = 0; i < 4; i++) {
                int s = tid + i * THRP;
                wr[i] = *reinterpret_cast<const uint4*>(
                    Wg + (size_t)(s >> 4) * KTOT + k0 + (s & 15) * 8);
            }
#pragma unroll
            for (int i = 0; i < 4; i++) {
                int s = tid + i * THRP;
                ar[i] = *reinterpret_cast<const uint4*>(
                    Xg + (size_t)(k0 + (s >> 3)) * Bd + (s & 7) * 8);
            }
        }

        unsigned aBase = sptr(sWc + (wm * 16 + (lane & 15)) * WPAD + (lane >> 4) * 8);
        unsigned bBase = sptr(sAc + (lane & 15) * APAD + wn * 32 + (lane >> 4) * 8);
#pragma unroll
        for (int kk = 0; kk < KC / 16; kk++) {
            unsigned a0, a1, a2, a3;
            ldsm4(a0, a1, a2, a3, aBase + kk * 32);
#pragma unroll
            for (int nb2 = 0; nb2 < 2; nb2++) {
                unsigned b0, b1, b2, b3;
                ldsm4t(b0, b1, b2, b3,
                       bBase + (unsigned)((kk * 16 * APAD + nb2 * 16) * 2));
                mma16816(acc[nb2 * 2 + 0], a0, a1, a2, a3, b0, b1);
                mma16816(acc[nb2 * 2 + 1], a0, a1, a2, a3, b2, b3);
            }
        }
        __syncthreads();
    }

    {
        int rbase = wm * 16 + (lane >> 2);
        float bs0 = bias[rbase], bs1 = bias[rbase + 8];
#pragma unroll
        for (int nb = 0; nb < 4; nb++) {
            int cb = wn * 32 + nb * 8 + (lane & 3) * 2;
            sG[rbase * GPAD + cb]           = acc[nb][0] + bs0;
            sG[rbase * GPAD + cb + 1]       = acc[nb][1] + bs0;
            sG[(rbase + 8) * GPAD + cb]     = acc[nb][2] + bs1;
            sG[(rbase + 8) * GPAD + cb + 1] = acc[nb][3] + bs1;
        }
    }
    __syncthreads();
}

__global__ void __launch_bounds__(THRP)
proj_kernel(float* __restrict__ out) {
    extern __shared__ char smem[];
    __half* sW = reinterpret_cast<__half*>(smem);
    __half* sA = reinterpret_cast<__half*>(smem + SMEM_W_OLD);
    float*  sG = reinterpret_cast<float*>(smem + SMEM_W_OLD + SMEM_A_OLD);

    const int tid = threadIdx.x, lane = tid & 31, wid = tid >> 5;
    const int bx = blockIdx.x;   // out-row block of 64 (16 blocks)
    const int t  = blockIdx.y;   // time step

    gemm64_old<Hd>(&g_WoutH[bx * 64][0], &g_H1all[t][0][0],
                   sW, sA, sG, &g_bout[bx * 64], tid, lane, wid);

#pragma unroll
    for (int e = 0; e < 16; e++) {
        int idx = tid + e * THRP;
        int b = idx >> 6, oo = idx & 63;
        out[((size_t)(t * Bd + b)) * OUTD + bx * 64 + oo] = sG[oo * GPAD + b];
    }
}

// ------------------------------- entry point -------------------------------
extern "C" void kernel_launch(void* const* d_in, const int* in_sizes, int n_in,
                              void* d_out, int out_size) {
    const float* h0   = (const float*)d_in[0];
    const float* c0   = (const float*)d_in[1];
    const float* Wih  = (const float*)d_in[2];
    const float* Whh  = (const float*)d_in[3];
    const float* bih  = (const float*)d_in[4];
    const float* bhh  = (const float*)d_in[5];
    const float* Wout = (const float*)d_in[6];
    const float* bout = (const float*)d_in[7];
    float* out = (float*)d_out;

    cudaFuncSetAttribute(lstm_main, cudaFuncAttributeMaxDynamicSharedMemorySize, SMEM_MAIN);
    cudaFuncSetAttribute(proj_kernel, cudaFuncAttributeMaxDynamicSharedMemorySize, SMEM_PROJ);

    pack_w_kernel<<<32768, 256>>>(Wih, Whh);
    pack_wout_kernel<<<2048, 256>>>(Wout);
    pack_misc_kernel<<<512, 256>>>(h0, bih, bhh, bout);  // also resets g_count
    lstm_main<<<NCTA, THRM, SMEM_MAIN>>>(c0);
    proj_kernel<<<dim3(16, Td), THRP, SMEM_PROJ>>>(out);
}

// round 11
// speedup vs baseline: 1.4953x; 1.4953x over previous
#include <cuda_runtime.h>
#include <cuda_fp16.h>
#include <cstdint>

#define Ld    2
#define Hd    2048
#define OUTD  1024
#define Bd    64
#define Td    256
#define NCTA  128
#define THRM  256
#define THRP  256
#define KC    128
#define ST    4

#define APAD  72
#define GPAD  68
#define PPAD  68
#define WPAD  136   // proj path only

// lstm_main smem: 4-stage ring (W 16K + B 18K per stage) + sP + sG
#define WB        16384
#define STB       (WB + KC * APAD * 2)       // 34816
#define SP_OFF    (ST * STB)                 // 139264
#define SG_OFF    (SP_OFF + 64 * PPAD * 4)   // 156672
#define SMEM_MAIN (SG_OFF + 64 * GPAD * 4)   // 174080

// proj smem
#define SMEM_A_OLD (2 * KC * APAD * 2)
#define SMEM_W_OLD (2 * 64 * WPAD * 2)
#define SMEM_G_OLD (64 * GPAD * 4)
#define SMEM_PROJ  (SMEM_W_OLD + SMEM_A_OLD + SMEM_G_OLD)

// ----------------------------- device globals ------------------------------
// W fragments: per (l,ct,chunk): [w4][kk4][mblk2][lane32] uint4 (1024/chunk)
__device__ __align__(16) uint4  g_Wf[(size_t)Ld * NCTA * 32 * 1024];  // 128 MB
__device__ __align__(16) __half g_WoutH[OUTD][Hd];
__device__ float  g_bias[Ld][NCTA][64];
__device__ float  g_bout[OUTD];
__device__ __align__(16) __half g_H0[2][Hd][Bd];      // layer-0 h ping-pong [k][b]
__device__ __align__(16) __half g_H1all[Td][Hd][Bd];  // layer-1 h, all steps
__device__ __align__(16) __half g_H1init[Hd][Bd];
__device__ __align__(16) __half g_Xzero[Hd][Bd];
__device__ unsigned g_count;

// ------------------------------ PTX helpers --------------------------------
__device__ __forceinline__ unsigned sptr(const void* p) {
    return (unsigned)__cvta_generic_to_shared(p);
}
__device__ __forceinline__ void cpa16(unsigned dst, const void* src) {
    asm volatile("cp.async.cg.shared.global [%0], [%1], 16;\n" :: "r"(dst), "l"(src));
}
__device__ __forceinline__ void cpa_commit() {
    asm volatile("cp.async.commit_group;\n" ::: "memory");
}
template <int N>
__device__ __forceinline__ void cpa_wait() {
    asm volatile("cp.async.wait_group %0;\n" :: "n"(N) : "memory");
}
__device__ __forceinline__ void ldsm4(unsigned& r0, unsigned& r1, unsigned& r2,
                                      unsigned& r3, unsigned a) {
    asm volatile("ldmatrix.sync.aligned.m8n8.x4.shared.b16 {%0,%1,%2,%3},[%4];\n"
                 : "=r"(r0), "=r"(r1), "=r"(r2), "=r"(r3) : "r"(a));
}
__device__ __forceinline__ void ldsm4t(unsigned& r0, unsigned& r1, unsigned& r2,
                                       unsigned& r3, unsigned a) {
    asm volatile("ldmatrix.sync.aligned.m8n8.x4.trans.shared.b16 {%0,%1,%2,%3},[%4];\n"
                 : "=r"(r0), "=r"(r1), "=r"(r2), "=r"(r3) : "r"(a));
}
__device__ __forceinline__ void mma16816(float* d, unsigned a0, unsigned a1,
                                         unsigned a2, unsigned a3,
                                         unsigned b0, unsigned b1) {
    asm volatile(
        "mma.sync.aligned.m16n8k16.row.col.f32.f16.f16.f32 "
        "{%0,%1,%2,%3},{%4,%5,%6,%7},{%8,%9},{%0,%1,%2,%3};\n"
        : "+f"(d[0]), "+f"(d[1]), "+f"(d[2]), "+f"(d[3])
        : "r"(a0), "r"(a1), "r"(a2), "r"(a3), "r"(b0), "r"(b1));
}
__device__ __forceinline__ float sgm(float x) { return 1.f / (1.f + __expf(-x)); }

__device__ __forceinline__ void gridbar(unsigned& target) {
    __syncthreads();
    if (threadIdx.x == 0) {
        __threadfence();
        target += (unsigned)gridDim.x;
        atomicAdd(&g_count, 1u);
        unsigned v;
        for (;;) {
            asm volatile("ld.acquire.gpu.global.u32 %0, [%1];" : "=r"(v) : "l"(&g_count));
            if (v >= target) break;
            __nanosleep(32);
        }
    }
    __syncthreads();
}

// ------------------------------ prep kernels -------------------------------
// Fragment pack: w = wm*2+wk (wm: 32-row half, wk: 64-k slice), kk: k16 step,
// mblk: 16-row block. Lane regs = W[(r,k),(r+8,k),(r,k+8),(r+8,k+8)] half2s.
__global__ void pack_w_kernel(const float* __restrict__ Wih,
                              const float* __restrict__ Whh) {
    int idx = blockIdx.x * blockDim.x + threadIdx.x;   // 8,388,608
    int lane = idx & 31;
    int mblk = (idx >> 5) & 1;
    int kk   = (idx >> 6) & 3;
    int w    = (idx >> 8) & 3;
    int kc   = (idx >> 10) & 31;
    int ct   = (idx >> 15) & 127;
    int l    = idx >> 22;
    if (l >= Ld) return;
    int wm = w >> 1, wk = w & 1;
    int r0 = wm * 32 + mblk * 16 + (lane >> 2);
    int k0 = kc * 128 + wk * 64 + kk * 16 + (lane & 3) * 2;

    auto ld2 = [&](int r, int k) -> float2 {
        int grow = (r >> 4) * 2048 + ct * 16 + (r & 15);
        const float* s = (k < 2048)
            ? (Wih + ((size_t)(l * 8192 + grow)) * 2048 + k)
            : (Whh + ((size_t)(l * 8192 + grow)) * 2048 + (k - 2048));
        return *reinterpret_cast<const float2*>(s);
    };
    float2 v0 = ld2(r0,     k0);
    float2 v1 = ld2(r0 + 8, k0);
    float2 v2 = ld2(r0,     k0 + 8);
    float2 v3 = ld2(r0 + 8, k0 + 8);

    __half2 h0 = __floats2half2_rn(v0.x, v0.y);
    __half2 h1 = __floats2half2_rn(v1.x, v1.y);
    __half2 h2 = __floats2half2_rn(v2.x, v2.y);
    __half2 h3 = __floats2half2_rn(v3.x, v3.y);
    uint4 o;
    o.x = *reinterpret_cast<unsigned*>(&h0);
    o.y = *reinterpret_cast<unsigned*>(&h1);
    o.z = *reinterpret_cast<unsigned*>(&h2);
    o.w = *reinterpret_cast<unsigned*>(&h3);

    size_t off = (((((size_t)(l * NCTA + ct) * 32 + kc) * 4 + w) * 4 + kk) * 2 + mblk)
                 * 32 + lane;
    g_Wf[off] = o;
}

__global__ void pack_wout_kernel(const float* __restrict__ Wout) {
    int idx = blockIdx.x * blockDim.x + threadIdx.x;
    int k0 = (idx & 511) * 4;
    int row = idx >> 9;
    if (row >= OUTD) return;
    float4 v = *reinterpret_cast<const float4*>(Wout + (size_t)row * Hd + k0);
    __half2* dst = reinterpret_cast<__half2*>(&g_WoutH[row][k0]);
    dst[0] = __floats2half2_rn(v.x, v.y);
    dst[1] = __floats2half2_rn(v.z, v.w);
}

__global__ void pack_misc_kernel(const float* __restrict__ h0,
                                 const float* __restrict__ bih,
                                 const float* __restrict__ bhh,
                                 const float* __restrict__ bout) {
    int i = blockIdx.x * blockDim.x + threadIdx.x;   // 131072
    if (i == 0) g_count = 0u;
    if (i < OUTD) g_bout[i] = bout[i];
    if (i < Ld * NCTA * 64) {
        int r = i & 63, ct = (i >> 6) & 127, l = i >> 13;
        int row = (r >> 4) * 2048 + ct * 16 + (r & 15);
        g_bias[l][ct][r] = bih[l * 8192 + row] + bhh[l * 8192 + row];
    }
    if (i < Hd * Bd) {
        int b = i & 63, j = i >> 6;
        g_H0[1][j][b]  = __float2half_rn(h0[(size_t)b * Hd + j]);
        g_H1init[j][b] = __float2half_rn(h0[(size_t)(Bd + b) * Hd + j]);
        g_Xzero[j][b]  = __float2half_rn(0.f);
    }
}

// ----------------------- chunk loader (W + B via cp.async) ------------------
__device__ __forceinline__ void issue_chunk(unsigned su, int stage,
                                            const uint4* __restrict__ Wc,
                                            const __half* __restrict__ Bs,
                                            int tid) {
    unsigned wb = su + stage * STB;
    unsigned bb = wb + WB;
#pragma unroll
    for (int it = 0; it < 8; it++) {
        int u = tid + it * THRM;          // 0..2047
        if (u < 1024) {                   // W: 1024 uint4, contiguous
            cpa16(wb + (unsigned)(u * 16), Wc + u);
        } else {                          // B: 128 rows x 128 B into APAD rows
            int v = u - 1024;
            int row = v >> 3, col8 = (v & 7) * 8;
            cpa16(bb + (unsigned)((row * APAD + col8) * 2),
                  Bs + (size_t)row * Bd + col8);
        }
    }
}

// --------------------------- gates GEMM (8 warps) ---------------------------
// D[64][64] = W[64][4096] x act[4096][64]. Warp grid wm2 x wn2 x wk2.
__device__ __forceinline__ void gemm_gates(const uint4* __restrict__ Wf,
                                           const __half* __restrict__ Xg,
                                           const __half* __restrict__ Hg,
                                           char* smem,
                                           const float* __restrict__ bias,
                                           int tid, int lane, int wid) {
    const int wm = wid >> 2, wn = (wid >> 1) & 1, wk = wid & 1;
    const unsigned su = sptr(smem);
    float acc[2][4][4];
#pragma unroll
    for (int a = 0; a < 2; a++)
#pragma unroll
        for (int b = 0; b < 4; b++)
#pragma unroll
            for (int c = 0; c < 4; c++) acc[a][b][c] = 0.f;

    // prologue: chunks 0..2
#pragma unroll
    for (int pc = 0; pc < ST - 1; pc++) {
        const __half* Bs = (pc < 16) ? (Xg + (size_t)pc * KC * Bd)
                                     : (Hg + (size_t)(pc - 16) * KC * Bd);
        issue_chunk(su, pc & (ST - 1), Wf + pc * 1024, Bs, tid);
        cpa_commit();
    }

#pragma unroll 1
    for (int kc = 0; kc < 32; kc++) {
        cpa_wait<ST - 2>();    // chunk kc landed
        __syncthreads();       // stage (kc+3)&3 = (kc-1)&3 fully consumed

        int ni = kc + ST - 1;
        if (ni < 32) {
            const __half* Bs = (ni < 16) ? (Xg + (size_t)ni * KC * Bd)
                                         : (Hg + (size_t)(ni - 16) * KC * Bd);
            issue_chunk(su, ni & (ST - 1), Wf + ni * 1024, Bs, tid);
        }
        cpa_commit();

        const char* stg = smem + (kc & (ST - 1)) * STB;
        const char* wst = stg + (wm * 2 + wk) * 4096;
        uint4 w[8];
#pragma unroll
        for (int kk = 0; kk < 4; kk++)
#pragma unroll
            for (int mb = 0; mb < 2; mb++)
                w[kk * 2 + mb] = *reinterpret_cast<const uint4*>(
                    wst + kk * 1024 + mb * 512 + lane * 16);

        unsigned bB = su + (kc & (ST - 1)) * STB + WB
                    + (unsigned)(((wk * 64 + (lane & 15)) * APAD
                                  + wn * 32 + (lane >> 4) * 8) * 2);
#pragma unroll
        for (int kk = 0; kk < 4; kk++) {
            unsigned bk = bB + (unsigned)(kk * 16 * APAD * 2);
#pragma unroll
            for (int n2 = 0; n2 < 2; n2++) {
                unsigned b0, b1, b2, b3;
                ldsm4t(b0, b1, b2, b3, bk + (unsigned)(n2 * 32));
                uint4 A0 = w[kk * 2 + 0], A1 = w[kk * 2 + 1];
                mma16816(acc[0][n2 * 2 + 0], A0.x, A0.y, A0.z, A0.w, b0, b1);
                mma16816(acc[0][n2 * 2 + 1], A0.x, A0.y, A0.z, A0.w, b2, b3);
                mma16816(acc[1][n2 * 2 + 0], A1.x, A1.y, A1.z, A1.w, b0, b1);
                mma16816(acc[1][n2 * 2 + 1], A1.x, A1.y, A1.z, A1.w, b2, b3);
            }
        }
    }
    __syncthreads();

    // 2-way k reduction
    float* sP = reinterpret_cast<float*>(smem + SP_OFF);
    float* sG = reinterpret_cast<float*>(smem + SG_OFF);
    const int gid = lane >> 2, tig = lane & 3;
    if (wk == 1) {
#pragma unroll
        for (int mb = 0; mb < 2; mb++) {
            int r = wm * 32 + mb * 16 + gid;
#pragma unroll
            for (int nb = 0; nb < 4; nb++) {
                int c = wn * 32 + nb * 8 + tig * 2;
                *reinterpret_cast<float2*>(&sP[r * PPAD + c]) =
                    make_float2(acc[mb][nb][0], acc[mb][nb][1]);
                *reinterpret_cast<float2*>(&sP[(r + 8) * PPAD + c]) =
                    make_float2(acc[mb][nb][2], acc[mb][nb][3]);
            }
        }
    }
    __syncthreads();
    if (wk == 0) {
#pragma unroll
        for (int mb = 0; mb < 2; mb++) {
            int r = wm * 32 + mb * 16 + gid;
            float bv0 = bias[r], bv1 = bias[r + 8];
#pragma unroll
            for (int nb = 0; nb < 4; nb++) {
                int c = wn * 32 + nb * 8 + tig * 2;
                float2 u0 = *reinterpret_cast<const float2*>(&sP[r * PPAD + c]);
                float2 u1 = *reinterpret_cast<const float2*>(&sP[(r + 8) * PPAD + c]);
                sG[r * GPAD + c]           = acc[mb][nb][0] + u0.x + bv0;
                sG[r * GPAD + c + 1]       = acc[mb][nb][1] + u0.y + bv0;
                sG[(r + 8) * GPAD + c]     = acc[mb][nb][2] + u1.x + bv1;
                sG[(r + 8) * GPAD + c + 1] = acc[mb][nb][3] + u1.y + bv1;
            }
        }
    }
    __syncthreads();
}

__device__ __forceinline__ void pointwise(const float* sG, float* cst,
                                          __half* Hout, int ct, int tid) {
#pragma unroll
    for (int e = 0; e < 4; e++) {
        int idx = tid + e * THRM;        // 16 hidden x 64 batch
        int b = idx & 63, jj = idx >> 6;
        float gi = sG[jj * GPAD + b];
        float gf = sG[(16 + jj) * GPAD + b];
        float gg = sG[(32 + jj) * GPAD + b];
        float go = sG[(48 + jj) * GPAD + b];
        float c = sgm(gf) * cst[e] + sgm(gi) * tanhf(gg);
        cst[e] = c;
        Hout[(ct * 16 + jj) * Bd + b] = __float2half_rn(sgm(go) * tanhf(c));
    }
}

// ------------------------------- main kernel -------------------------------
__global__ void __launch_bounds__(THRM, 1)
lstm_main(const float* __restrict__ c0) {
    extern __shared__ char smem[];
    float* sG = reinterpret_cast<float*>(smem + SG_OFF);

    const int tid = threadIdx.x, lane = tid & 31, wid = tid >> 5;
    const int ct = blockIdx.x;

    float cst0[4], cst1[4];
#pragma unroll
    for (int e = 0; e < 4; e++) {
        int idx = tid + e * THRM;
        int b = idx & 63, j = ct * 16 + (idx >> 6);
        cst0[e] = c0[(size_t)b * Hd + j];
        cst1[e] = c0[(size_t)(Bd + b) * Hd + j];
    }

    const uint4* W0 = g_Wf + ((size_t)0 * NCTA + ct) * 32768;
    const uint4* W1 = g_Wf + ((size_t)1 * NCTA + ct) * 32768;
    const float* bias0 = &g_bias[0][ct][0];
    const float* bias1 = &g_bias[1][ct][0];
    unsigned target = 0;

    for (int t = 0; t < Td; t++) {
        const int p = t & 1;
        const __half* X0  = (t == 0) ? &g_Xzero[0][0] : &g_H1all[t - 1][0][0];
        const __half* Hp0 = &g_H0[p ^ 1][0][0];
        gemm_gates(W0, X0, Hp0, smem, bias0, tid, lane, wid);
        pointwise(sG, cst0, &g_H0[p][0][0], ct, tid);
        gridbar(target);

        const __half* X1  = &g_H0[p][0][0];
        const __half* Hp1 = (t == 0) ? &g_H1init[0][0] : &g_H1all[t - 1][0][0];
        gemm_gates(W1, X1, Hp1, smem, bias1, tid, lane, wid);
        pointwise(sG, cst1, &g_H1all[t][0][0], ct, tid);
        gridbar(target);
    }
}

// -------------------- proj GEMM (off critical path) -------------------------
template <int KTOT>
__device__ __forceinline__ void gemm64_old(const __half* __restrict__ Wg,
                                           const __half* __restrict__ Xg,
                                           __half* sW, __half* sA, float* sG,
                                           const float* __restrict__ bias,
                                           int tid, int lane, int wid) {
    constexpr int NCHUNK = KTOT / KC;
    float acc[4][4];
#pragma unroll
    for (int i = 0; i < 4; i++)
#pragma unroll
        for (int j = 0; j < 4; j++) acc[i][j] = 0.f;
    const int wm = wid >> 1, wn = wid & 1;

    uint4 wr[4], ar[4];
#pragma unroll
    for (int i = 0; i < 4; i++) {
        int s = tid + i * THRP;
        wr[i] = *reinterpret_cast<const uint4*>(Wg + (size_t)(s >> 4) * KTOT + (s & 15) * 8);
    }
#pragma unroll
    for (int i = 0; i < 4; i++) {
        int s = tid + i * THRP;
        ar[i] = *reinterpret_cast<const uint4*>(Xg + (size_t)(s >> 3) * Bd + (s & 7) * 8);
    }

#pragma unroll 1
    for (int kc = 0; kc < NCHUNK; kc++) {
        __half* sWc = sW + (kc & 1) * 64 * WPAD;
        __half* sAc = sA + (kc & 1) * KC * APAD;
#pragma unroll
        for (int i = 0; i < 4; i++) {
            int s = tid + i * THRP;
            *reinterpret_cast<uint4*>(sWc + (s >> 4) * WPAD + (s & 15) * 8) = wr[i];
        }
#pragma unroll
        for (int i = 0; i < 4; i++) {
            int s = tid + i * THRP;
            *reinterpret_cast<uint4*>(sAc + (s >> 3) * APAD + (s & 7) * 8) = ar[i];
        }
        __syncthreads();

        if (kc + 1 < NCHUNK) {
            int k0 = (kc + 1) * KC;
#pragma unroll
            for (int i = 0; i < 4; i++) {
                int s = tid + i * THRP;
                wr[i] = *reinterpret_cast<const uint4*>(
                    Wg + (size_t)(s >> 4) * KTOT + k0 + (s & 15) * 8);
            }
#pragma unroll
            for (int i = 0; i < 4; i++) {
                int s = tid + i * THRP;
                ar[i] = *reinterpret_cast<const uint4*>(
                    Xg + (size_t)(k0 + (s >> 3)) * Bd + (s & 7) * 8);
            }
        }

        unsigned aBase = sptr(sWc + (wm * 16 + (lane & 15)) * WPAD + (lane >> 4) * 8);
        unsigned bBase = sptr(sAc + (lane & 15) * APAD + wn * 32 + (lane >> 4) * 8);
#pragma unroll
        for (int kk = 0; kk < KC / 16; kk++) {
            unsigned a0, a1, a2, a3;
            ldsm4(a0, a1, a2, a3, aBase + kk * 32);
#pragma unroll
            for (int nb2 = 0; nb2 < 2; nb2++) {
                unsigned b0, b1, b2, b3;
                ldsm4t(b0, b1, b2, b3,
                       bBase + (unsigned)((kk * 16 * APAD + nb2 * 16) * 2));
                mma16816(acc[nb2 * 2 + 0], a0, a1, a2, a3, b0, b1);
                mma16816(acc[nb2 * 2 + 1], a0, a1, a2, a3, b2, b3);
            }
        }
        __syncthreads();
    }

    {
        int rbase = wm * 16 + (lane >> 2);
        float bs0 = bias[rbase], bs1 = bias[rbase + 8];
#pragma unroll
        for (int nb = 0; nb < 4; nb++) {
            int cb = wn * 32 + nb * 8 + (lane & 3) * 2;
            sG[rbase * GPAD + cb]           = acc[nb][0] + bs0;
            sG[rbase * GPAD + cb + 1]       = acc[nb][1] + bs0;
            sG[(rbase + 8) * GPAD + cb]     = acc[nb][2] + bs1;
            sG[(rbase + 8) * GPAD + cb + 1] = acc[nb][3] + bs1;
        }
    }
    __syncthreads();
}

__global__ void __launch_bounds__(THRP)
proj_kernel(float* __restrict__ out) {
    extern __shared__ char smem[];
    __half* sW = reinterpret_cast<__half*>(smem);
    __half* sA = reinterpret_cast<__half*>(smem + SMEM_W_OLD);
    float*  sG = reinterpret_cast<float*>(smem + SMEM_W_OLD + SMEM_A_OLD);

    const int tid = threadIdx.x, lane = tid & 31, wid = tid >> 5;
    const int bx = blockIdx.x;
    const int t  = blockIdx.y;

    gemm64_old<Hd>(&g_WoutH[bx * 64][0], &g_H1all[t][0][0],
                   sW, sA, sG, &g_bout[bx * 64], tid, lane, wid);

#pragma unroll
    for (int e = 0; e < 16; e++) {
        int idx = tid + e * THRP;
        int b = idx >> 6, oo = idx & 63;
        out[((size_t)(t * Bd + b)) * OUTD + bx * 64 + oo] = sG[oo * GPAD + b];
    }
}

// ------------------------------- entry point -------------------------------
extern "C" void kernel_launch(void* const* d_in, const int* in_sizes, int n_in,
                              void* d_out, int out_size) {
    const float* h0   = (const float*)d_in[0];
    const float* c0   = (const float*)d_in[1];
    const float* Wih  = (const float*)d_in[2];
    const float* Whh  = (const float*)d_in[3];
    const float* bih  = (const float*)d_in[4];
    const float* bhh  = (const float*)d_in[5];
    const float* Wout = (const float*)d_in[6];
    const float* bout = (const float*)d_in[7];
    float* out = (float*)d_out;

    cudaFuncSetAttribute(lstm_main, cudaFuncAttributeMaxDynamicSharedMemorySize, SMEM_MAIN);
    cudaFuncSetAttribute(proj_kernel, cudaFuncAttributeMaxDynamicSharedMemorySize, SMEM_PROJ);

    pack_w_kernel<<<32768, 256>>>(Wih, Whh);
    pack_wout_kernel<<<2048, 256>>>(Wout);
    pack_misc_kernel<<<512, 256>>>(h0, bih, bhh, bout);  // also resets g_count
    lstm_main<<<NCTA, THRM, SMEM_MAIN>>>(c0);
    proj_kernel<<<dim3(16, Td), THRP, SMEM_PROJ>>>(out);
}

// round 12
// speedup vs baseline: 1.5019x; 1.0044x over previous
#include <cuda_runtime.h>
#include <cuda_fp16.h>
#include <cstdint>

#define Ld    2
#define Hd    2048
#define OUTD  1024
#define Bd    64
#define Td    256
#define NCTA  128
#define THRM  512   // 16 warps
#define THRP  256
#define KC    128
#define ST    4

#define APAD  72
#define GPAD  68
#define PPAD  68
#define WPAD  136   // proj path only

// lstm_main smem: 4-stage ring (W 16K + B 18K per stage) + sP(3) + sG
#define WB        16384
#define STB       (WB + KC * APAD * 2)       // 34816
#define SP_OFF    (ST * STB)                 // 139264
#define SG_OFF    (SP_OFF + 3 * 64 * PPAD * 4)   // 191488
#define SMEM_MAIN (SG_OFF + 64 * GPAD * 4)   // 208896

// proj smem
#define SMEM_A_OLD (2 * KC * APAD * 2)
#define SMEM_W_OLD (2 * 64 * WPAD * 2)
#define SMEM_G_OLD (64 * GPAD * 4)
#define SMEM_PROJ  (SMEM_W_OLD + SMEM_A_OLD + SMEM_G_OLD)

// ----------------------------- device globals ------------------------------
// W fragments per (l,ct,chunk): [wm2*wk4][kk2][mblk2][lane32] uint4 (1024)
__device__ __align__(16) uint4  g_Wf[(size_t)Ld * NCTA * 32 * 1024];  // 128 MB
__device__ __align__(16) __half g_WoutH[OUTD][Hd];
__device__ float  g_bias[Ld][NCTA][64];
__device__ float  g_bout[OUTD];
__device__ __align__(16) __half g_H0[2][Hd][Bd];      // layer-0 h ping-pong [k][b]
__device__ __align__(16) __half g_H1all[Td][Hd][Bd];  // layer-1 h, all steps
__device__ __align__(16) __half g_H1init[Hd][Bd];
__device__ __align__(16) __half g_Xzero[Hd][Bd];
__device__ unsigned g_count;

// ------------------------------ PTX helpers --------------------------------
__device__ __forceinline__ unsigned sptr(const void* p) {
    return (unsigned)__cvta_generic_to_shared(p);
}
__device__ __forceinline__ void cpa16(unsigned dst, const void* src) {
    asm volatile("cp.async.cg.shared.global [%0], [%1], 16;\n" :: "r"(dst), "l"(src));
}
__device__ __forceinline__ void cpa_commit() {
    asm volatile("cp.async.commit_group;\n" ::: "memory");
}
template <int N>
__device__ __forceinline__ void cpa_wait() {
    asm volatile("cp.async.wait_group %0;\n" :: "n"(N) : "memory");
}
__device__ __forceinline__ void ldsm4(unsigned& r0, unsigned& r1, unsigned& r2,
                                      unsigned& r3, unsigned a) {
    asm volatile("ldmatrix.sync.aligned.m8n8.x4.shared.b16 {%0,%1,%2,%3},[%4];\n"
                 : "=r"(r0), "=r"(r1), "=r"(r2), "=r"(r3) : "r"(a));
}
__device__ __forceinline__ void ldsm4t(unsigned& r0, unsigned& r1, unsigned& r2,
                                       unsigned& r3, unsigned a) {
    asm volatile("ldmatrix.sync.aligned.m8n8.x4.trans.shared.b16 {%0,%1,%2,%3},[%4];\n"
                 : "=r"(r0), "=r"(r1), "=r"(r2), "=r"(r3) : "r"(a));
}
__device__ __forceinline__ void mma16816(float* d, unsigned a0, unsigned a1,
                                         unsigned a2, unsigned a3,
                                         unsigned b0, unsigned b1) {
    asm volatile(
        "mma.sync.aligned.m16n8k16.row.col.f32.f16.f16.f32 "
        "{%0,%1,%2,%3},{%4,%5,%6,%7},{%8,%9},{%0,%1,%2,%3};\n"
        : "+f"(d[0]), "+f"(d[1]), "+f"(d[2]), "+f"(d[3])
        : "r"(a0), "r"(a1), "r"(a2), "r"(a3), "r"(b0), "r"(b1));
}
__device__ __forceinline__ float sgm(float x) { return 1.f / (1.f + __expf(-x)); }

__device__ __forceinline__ void gridbar(unsigned& target) {
    __syncthreads();
    if (threadIdx.x == 0) {
        __threadfence();
        target += (unsigned)gridDim.x;
        atomicAdd(&g_count, 1u);
        unsigned v;
        for (;;) {
            asm volatile("ld.acquire.gpu.global.u32 %0, [%1];" : "=r"(v) : "l"(&g_count));
            if (v >= target) break;
            __nanosleep(32);
        }
    }
    __syncthreads();
}

// ------------------------------ prep kernels -------------------------------
// Warp wid: wm = wid>>3 (32-row half), wn = (wid>>2)&1 (n32), wk = wid&3 (k32).
// Frag order per warp slice: [kk2][mblk2]; lane regs = std m16k16 A fragment.
__global__ void pack_w_kernel(const float* __restrict__ Wih,
                              const float* __restrict__ Whh) {
    int idx = blockIdx.x * blockDim.x + threadIdx.x;   // 8,388,608
    int lane = idx & 31;
    int mblk = (idx >> 5) & 1;
    int kk   = (idx >> 6) & 1;
    int wk   = (idx >> 7) & 3;
    int wm   = (idx >> 9) & 1;
    int kc   = (idx >> 10) & 31;
    int ct   = (idx >> 15) & 127;
    int l    = idx >> 22;
    if (l >= Ld) return;
    int r0 = wm * 32 + mblk * 16 + (lane >> 2);
    int k0 = kc * 128 + wk * 32 + kk * 16 + (lane & 3) * 2;

    auto ld2 = [&](int r, int k) -> float2 {
        int grow = (r >> 4) * 2048 + ct * 16 + (r & 15);
        const float* s = (k < 2048)
            ? (Wih + ((size_t)(l * 8192 + grow)) * 2048 + k)
            : (Whh + ((size_t)(l * 8192 + grow)) * 2048 + (k - 2048));
        return *reinterpret_cast<const float2*>(s);
    };
    float2 v0 = ld2(r0,     k0);
    float2 v1 = ld2(r0 + 8, k0);
    float2 v2 = ld2(r0,     k0 + 8);
    float2 v3 = ld2(r0 + 8, k0 + 8);

    __half2 h0 = __floats2half2_rn(v0.x, v0.y);
    __half2 h1 = __floats2half2_rn(v1.x, v1.y);
    __half2 h2 = __floats2half2_rn(v2.x, v2.y);
    __half2 h3 = __floats2half2_rn(v3.x, v3.y);
    uint4 o;
    o.x = *reinterpret_cast<unsigned*>(&h0);
    o.y = *reinterpret_cast<unsigned*>(&h1);
    o.z = *reinterpret_cast<unsigned*>(&h2);
    o.w = *reinterpret_cast<unsigned*>(&h3);

    size_t off = ((((size_t)(l * NCTA + ct) * 32 + kc)) * 1024)
               + (size_t)((wm * 4 + wk) * 128 + kk * 64 + mblk * 32 + lane);
    g_Wf[off] = o;
}

__global__ void pack_wout_kernel(const float* __restrict__ Wout) {
    int idx = blockIdx.x * blockDim.x + threadIdx.x;
    int k0 = (idx & 511) * 4;
    int row = idx >> 9;
    if (row >= OUTD) return;
    float4 v = *reinterpret_cast<const float4*>(Wout + (size_t)row * Hd + k0);
    __half2* dst = reinterpret_cast<__half2*>(&g_WoutH[row][k0]);
    dst[0] = __floats2half2_rn(v.x, v.y);
    dst[1] = __floats2half2_rn(v.z, v.w);
}

__global__ void pack_misc_kernel(const float* __restrict__ h0,
                                 const float* __restrict__ bih,
                                 const float* __restrict__ bhh,
                                 const float* __restrict__ bout) {
    int i = blockIdx.x * blockDim.x + threadIdx.x;   // 131072
    if (i == 0) g_count = 0u;
    if (i < OUTD) g_bout[i] = bout[i];
    if (i < Ld * NCTA * 64) {
        int r = i & 63, ct = (i >> 6) & 127, l = i >> 13;
        int row = (r >> 4) * 2048 + ct * 16 + (r & 15);
        g_bias[l][ct][r] = bih[l * 8192 + row] + bhh[l * 8192 + row];
    }
    if (i < Hd * Bd) {
        int b = i & 63, j = i >> 6;
        g_H0[1][j][b]  = __float2half_rn(h0[(size_t)b * Hd + j]);
        g_H1init[j][b] = __float2half_rn(h0[(size_t)(Bd + b) * Hd + j]);
        g_Xzero[j][b]  = __float2half_rn(0.f);
    }
}

// ----------------------- chunk loader (W + B via cp.async) ------------------
__device__ __forceinline__ void issue_chunk(unsigned su, int stage,
                                            const uint4* __restrict__ Wc,
                                            const __half* __restrict__ Bs,
                                            int tid) {
    unsigned wb = su + stage * STB;
    unsigned bb = wb + WB;
#pragma unroll
    for (int it = 0; it < 4; it++) {
        int u = tid + it * THRM;          // 0..2047
        if (u < 1024) {                   // W: 1024 uint4, contiguous
            cpa16(wb + (unsigned)(u * 16), Wc + u);
        } else {                          // B: 128 rows x 128 B into APAD rows
            int v = u - 1024;
            int row = v >> 3, col8 = (v & 7) * 8;
            cpa16(bb + (unsigned)((row * APAD + col8) * 2),
                  Bs + (size_t)row * Bd + col8);
        }
    }
}

// --------------------------- gates GEMM (16 warps) ---------------------------
// D[64][64] = W[64][4096] x act[4096][64]. Warp grid wm2 x wn2 x wk4.
__device__ __forceinline__ void gemm_gates(const uint4* __restrict__ Wf,
                                           const __half* __restrict__ Xg,
                                           const __half* __restrict__ Hg,
                                           char* smem,
                                           const float* __restrict__ bias,
                                           int tid, int lane, int wid) {
    const int wm = wid >> 3, wn = (wid >> 2) & 1, wk = wid & 3;
    const unsigned su = sptr(smem);
    float acc[2][4][4];
#pragma unroll
    for (int a = 0; a < 2; a++)
#pragma unroll
        for (int b = 0; b < 4; b++)
#pragma unroll
            for (int c = 0; c < 4; c++) acc[a][b][c] = 0.f;

    // prologue: chunks 0..2
#pragma unroll
    for (int pc = 0; pc < ST - 1; pc++) {
        const __half* Bs = (pc < 16) ? (Xg + (size_t)pc * KC * Bd)
                                     : (Hg + (size_t)(pc - 16) * KC * Bd);
        issue_chunk(su, pc & (ST - 1), Wf + pc * 1024, Bs, tid);
        cpa_commit();
    }

#pragma unroll 1
    for (int kc = 0; kc < 32; kc++) {
        cpa_wait<ST - 2>();    // chunk kc landed
        __syncthreads();       // stage (kc-1)&3 fully consumed

        int ni = kc + ST - 1;
        if (ni < 32) {
            const __half* Bs = (ni < 16) ? (Xg + (size_t)ni * KC * Bd)
                                         : (Hg + (size_t)(ni - 16) * KC * Bd);
            issue_chunk(su, ni & (ST - 1), Wf + ni * 1024, Bs, tid);
        }
        cpa_commit();

        const char* stg = smem + (kc & (ST - 1)) * STB;
        const char* wst = stg + (wm * 4 + wk) * 2048;
        uint4 w[4];
#pragma unroll
        for (int kk = 0; kk < 2; kk++)
#pragma unroll
            for (int mb = 0; mb < 2; mb++)
                w[kk * 2 + mb] = *reinterpret_cast<const uint4*>(
                    wst + kk * 1024 + mb * 512 + lane * 16);

        unsigned bB = su + (kc & (ST - 1)) * STB + WB
                    + (unsigned)(((wk * 32 + (lane & 15)) * APAD
                                  + wn * 32 + (lane >> 4) * 8) * 2);
#pragma unroll
        for (int kk = 0; kk < 2; kk++) {
            unsigned bk = bB + (unsigned)(kk * 16 * APAD * 2);
#pragma unroll
            for (int n2 = 0; n2 < 2; n2++) {
                unsigned b0, b1, b2, b3;
                ldsm4t(b0, b1, b2, b3, bk + (unsigned)(n2 * 32));
                uint4 A0 = w[kk * 2 + 0], A1 = w[kk * 2 + 1];
                mma16816(acc[0][n2 * 2 + 0], A0.x, A0.y, A0.z, A0.w, b0, b1);
                mma16816(acc[0][n2 * 2 + 1], A0.x, A0.y, A0.z, A0.w, b2, b3);
                mma16816(acc[1][n2 * 2 + 0], A1.x, A1.y, A1.z, A1.w, b0, b1);
                mma16816(acc[1][n2 * 2 + 1], A1.x, A1.y, A1.z, A1.w, b2, b3);
            }
        }
    }
    __syncthreads();

    // 4-way k reduction
    float* sP = reinterpret_cast<float*>(smem + SP_OFF);
    float* sG = reinterpret_cast<float*>(smem + SG_OFF);
    const int gid = lane >> 2, tig = lane & 3;
    if (wk > 0) {
        float* P = sP + (wk - 1) * 64 * PPAD;
#pragma unroll
        for (int mb = 0; mb < 2; mb++) {
            int r = wm * 32 + mb * 16 + gid;
#pragma unroll
            for (int nb = 0; nb < 4; nb++) {
                int c = wn * 32 + nb * 8 + tig * 2;
                *reinterpret_cast<float2*>(&P[r * PPAD + c]) =
                    make_float2(acc[mb][nb][0], acc[mb][nb][1]);
                *reinterpret_cast<float2*>(&P[(r + 8) * PPAD + c]) =
                    make_float2(acc[mb][nb][2], acc[mb][nb][3]);
            }
        }
    }
    __syncthreads();
    if (wk == 0) {
#pragma unroll
        for (int mb = 0; mb < 2; mb++) {
            int r = wm * 32 + mb * 16 + gid;
            float bv0 = bias[r], bv1 = bias[r + 8];
#pragma unroll
            for (int nb = 0; nb < 4; nb++) {
                int c = wn * 32 + nb * 8 + tig * 2;
                float s00 = acc[mb][nb][0] + bv0, s01 = acc[mb][nb][1] + bv0;
                float s10 = acc[mb][nb][2] + bv1, s11 = acc[mb][nb][3] + bv1;
#pragma unroll
                for (int p = 0; p < 3; p++) {
                    const float* P = sP + p * 64 * PPAD;
                    float2 u0 = *reinterpret_cast<const float2*>(&P[r * PPAD + c]);
                    float2 u1 = *reinterpret_cast<const float2*>(&P[(r + 8) * PPAD + c]);
                    s00 += u0.x; s01 += u0.y; s10 += u1.x; s11 += u1.y;
                }
                sG[r * GPAD + c]           = s00;
                sG[r * GPAD + c + 1]       = s01;
                sG[(r + 8) * GPAD + c]     = s10;
                sG[(r + 8) * GPAD + c + 1] = s11;
            }
        }
    }
    __syncthreads();
}

__device__ __forceinline__ void pointwise(const float* sG, float* cst,
                                          __half* Hout, int ct, int tid) {
#pragma unroll
    for (int e = 0; e < 2; e++) {
        int idx = tid + e * THRM;        // 16 hidden x 64 batch
        int b = idx & 63, jj = idx >> 6;
        float gi = sG[jj * GPAD + b];
        float gf = sG[(16 + jj) * GPAD + b];
        float gg = sG[(32 + jj) * GPAD + b];
        float go = sG[(48 + jj) * GPAD + b];
        float c = sgm(gf) * cst[e] + sgm(gi) * tanhf(gg);
        cst[e] = c;
        Hout[(ct * 16 + jj) * Bd + b] = __float2half_rn(sgm(go) * tanhf(c));
    }
}

// ------------------------------- main kernel -------------------------------
__global__ void __launch_bounds__(THRM, 1)
lstm_main(const float* __restrict__ c0) {
    extern __shared__ char smem[];
    float* sG = reinterpret_cast<float*>(smem + SG_OFF);

    const int tid = threadIdx.x, lane = tid & 31, wid = tid >> 5;
    const int ct = blockIdx.x;

    float cst0[2], cst1[2];
#pragma unroll
    for (int e = 0; e < 2; e++) {
        int idx = tid + e * THRM;
        int b = idx & 63, j = ct * 16 + (idx >> 6);
        cst0[e] = c0[(size_t)b * Hd + j];
        cst1[e] = c0[(size_t)(Bd + b) * Hd + j];
    }

    const uint4* W0 = g_Wf + ((size_t)0 * NCTA + ct) * 32768;
    const uint4* W1 = g_Wf + ((size_t)1 * NCTA + ct) * 32768;
    const float* bias0 = &g_bias[0][ct][0];
    const float* bias1 = &g_bias[1][ct][0];
    unsigned target = 0;

    for (int t = 0; t < Td; t++) {
        const int p = t & 1;
        const __half* X0  = (t == 0) ? &g_Xzero[0][0] : &g_H1all[t - 1][0][0];
        const __half* Hp0 = &g_H0[p ^ 1][0][0];
        gemm_gates(W0, X0, Hp0, smem, bias0, tid, lane, wid);
        pointwise(sG, cst0, &g_H0[p][0][0], ct, tid);
        gridbar(target);

        const __half* X1  = &g_H0[p][0][0];
        const __half* Hp1 = (t == 0) ? &g_H1init[0][0] : &g_H1all[t - 1][0][0];
        gemm_gates(W1, X1, Hp1, smem, bias1, tid, lane, wid);
        pointwise(sG, cst1, &g_H1all[t][0][0], ct, tid);
        gridbar(target);
    }
}

// -------------------- proj GEMM (off critical path) -------------------------
template <int KTOT>
__device__ __forceinline__ void gemm64_old(const __half* __restrict__ Wg,
                                           const __half* __restrict__ Xg,
                                           __half* sW, __half* sA, float* sG,
                                           const float* __restrict__ bias,
                                           int tid, int lane, int wid) {
    constexpr int NCHUNK = KTOT / KC;
    float acc[4][4];
#pragma unroll
    for (int i = 0; i < 4; i++)
#pragma unroll
        for (int j = 0; j < 4; j++) acc[i][j] = 0.f;
    const int wm = wid >> 1, wn = wid & 1;

    uint4 wr[4], ar[4];
#pragma unroll
    for (int i = 0; i < 4; i++) {
        int s = tid + i * THRP;
        wr[i] = *reinterpret_cast<const uint4*>(Wg + (size_t)(s >> 4) * KTOT + (s & 15) * 8);
    }
#pragma unroll
    for (int i = 0; i < 4; i++) {
        int s = tid + i * THRP;
        ar[i] = *reinterpret_cast<const uint4*>(Xg + (size_t)(s >> 3) * Bd + (s & 7) * 8);
    }

#pragma unroll 1
    for (int kc = 0; kc < NCHUNK; kc++) {
        __half* sWc = sW + (kc & 1) * 64 * WPAD;
        __half* sAc = sA + (kc & 1) * KC * APAD;
#pragma unroll
        for (int i = 0; i < 4; i++) {
            int s = tid + i * THRP;
            *reinterpret_cast<uint4*>(sWc + (s >> 4) * WPAD + (s & 15) * 8) = wr[i];
        }
#pragma unroll
        for (int i = 0; i < 4; i++) {
            int s = tid + i * THRP;
            *reinterpret_cast<uint4*>(sAc + (s >> 3) * APAD + (s & 7) * 8) = ar[i];
        }
        __syncthreads();

        if (kc + 1 < NCHUNK) {
            int k0 = (kc + 1) * KC;
#pragma unroll
            for (int i = 0; i < 4; i++) {
                int s = tid + i * THRP;
                wr[i] = *reinterpret_cast<const uint4*>(
                    Wg + (size_t)(s >> 4) * KTOT + k0 + (s & 15) * 8);
            }
#pragma unroll
            for (int i = 0; i < 4; i++) {
                int s = tid + i * THRP;
                ar[i] = *reinterpret_cast<const uint4*>(
                    Xg + (size_t)(k0 + (s >> 3)) * Bd + (s & 7) * 8);
            }
        }

        unsigned aBase = sptr(sWc + (wm * 16 + (lane & 15)) * WPAD + (lane >> 4) * 8);
        unsigned bBase = sptr(sAc + (lane & 15) * APAD + wn * 32 + (lane >> 4) * 8);
#pragma unroll
        for (int kk = 0; kk < KC / 16; kk++) {
            unsigned a0, a1, a2, a3;
            ldsm4(a0, a1, a2, a3, aBase + kk * 32);
#pragma unroll
            for (int nb2 = 0; nb2 < 2; nb2++) {
                unsigned b0, b1, b2, b3;
                ldsm4t(b0, b1, b2, b3,
                       bBase + (unsigned)((kk * 16 * APAD + nb2 * 16) * 2));
                mma16816(acc[nb2 * 2 + 0], a0, a1, a2, a3, b0, b1);
                mma16816(acc[nb2 * 2 + 1], a0, a1, a2, a3, b2, b3);
            }
        }
        __syncthreads();
    }

    {
        int rbase = wm * 16 + (lane >> 2);
        float bs0 = bias[rbase], bs1 = bias[rbase + 8];
#pragma unroll
        for (int nb = 0; nb < 4; nb++) {
            int cb = wn * 32 + nb * 8 + (lane & 3) * 2;
            sG[rbase * GPAD + cb]           = acc[nb][0] + bs0;
            sG[rbase * GPAD + cb + 1]       = acc[nb][1] + bs0;
            sG[(rbase + 8) * GPAD + cb]     = acc[nb][2] + bs1;
            sG[(rbase + 8) * GPAD + cb + 1] = acc[nb][3] + bs1;
        }
    }
    __syncthreads();
}

__global__ void __launch_bounds__(THRP)
proj_kernel(float* __restrict__ out) {
    extern __shared__ char smem[];
    __half* sW = reinterpret_cast<__half*>(smem);
    __half* sA = reinterpret_cast<__half*>(smem + SMEM_W_OLD);
    float*  sG = reinterpret_cast<float*>(smem + SMEM_W_OLD + SMEM_A_OLD);

    const int tid = threadIdx.x, lane = tid & 31, wid = tid >> 5;
    const int bx = blockIdx.x;
    const int t  = blockIdx.y;

    gemm64_old<Hd>(&g_WoutH[bx * 64][0], &g_H1all[t][0][0],
                   sW, sA, sG, &g_bout[bx * 64], tid, lane, wid);

#pragma unroll
    for (int e = 0; e < 16; e++) {
        int idx = tid + e * THRP;
        int b = idx >> 6, oo = idx & 63;
        out[((size_t)(t * Bd + b)) * OUTD + bx * 64 + oo] = sG[oo * GPAD + b];
    }
}

// ------------------------------- entry point -------------------------------
extern "C" void kernel_launch(void* const* d_in, const int* in_sizes, int n_in,
                              void* d_out, int out_size) {
    const float* h0   = (const float*)d_in[0];
    const float* c0   = (const float*)d_in[1];
    const float* Wih  = (const float*)d_in[2];
    const float* Whh  = (const float*)d_in[3];
    const float* bih  = (const float*)d_in[4];
    const float* bhh  = (const float*)d_in[5];
    const float* Wout = (const float*)d_in[6];
    const float* bout = (const float*)d_in[7];
    float* out = (float*)d_out;

    cudaFuncSetAttribute(lstm_main, cudaFuncAttributeMaxDynamicSharedMemorySize, SMEM_MAIN);
    cudaFuncSetAttribute(proj_kernel, cudaFuncAttributeMaxDynamicSharedMemorySize, SMEM_PROJ);

    pack_w_kernel<<<32768, 256>>>(Wih, Whh);
    pack_wout_kernel<<<2048, 256>>>(Wout);
    pack_misc_kernel<<<512, 256>>>(h0, bih, bhh, bout);  // also resets g_count
    lstm_main<<<NCTA, THRM, SMEM_MAIN>>>(c0);
    proj_kernel<<<dim3(16, Td), THRP, SMEM_PROJ>>>(out);
}